// round 4
// baseline (speedup 1.0000x reference)
#include <cuda_runtime.h>
#include <cuda_bf16.h>
#include <math.h>
#include <stdint.h>

// Problem constants
#define S_LEN 2048
#define D_DIM 1024
#define H_NUM 16
#define HDIM  64
#define FF_DIM 4096
#define CCH   64
#define NCH   (S_LEN/CCH)

// ---------------- scratch (static device globals; no allocation) ----------
__device__ float g_h   [S_LEN*D_DIM];
__device__ float g_q   [S_LEN*D_DIM];
__device__ float g_k   [S_LEN*D_DIM];
__device__ float g_v   [S_LEN*D_DIM];
__device__ float g_attn[S_LEN*D_DIM];
__device__ float g_x2  [S_LEN*D_DIM];
__device__ float g_h2  [S_LEN*D_DIM];
__device__ float g_ff  [S_LEN*FF_DIM];
__device__ float g_kv  [H_NUM*NCH*HDIM*HDIM];
__device__ float g_kvp [H_NUM*NCH*HDIM*HDIM];
__device__ float g_zc  [H_NUM*NCH*HDIM];
__device__ float g_zp  [H_NUM*NCH*HDIM];

// ---------------- LayerNorm -------------------------------------------------
__global__ void ln_kernel(const float* __restrict__ x,
                          const float* __restrict__ g,
                          const float* __restrict__ b,
                          float* __restrict__ out) {
    int row = blockIdx.x;
    const float* xr = x + (size_t)row * D_DIM;
    float s = 0.f, s2 = 0.f;
    for (int i = threadIdx.x; i < D_DIM; i += 256) {
        float v = xr[i];
        s += v; s2 += v * v;
    }
    __shared__ float sh[64];
    for (int off = 16; off > 0; off >>= 1) {
        s  += __shfl_down_sync(0xffffffffu, s,  off);
        s2 += __shfl_down_sync(0xffffffffu, s2, off);
    }
    int w = threadIdx.x >> 5, l = threadIdx.x & 31;
    if (l == 0) { sh[w] = s; sh[w + 32] = s2; }
    __syncthreads();
    if (threadIdx.x == 0) {
        float ts = 0.f, ts2 = 0.f;
        for (int i = 0; i < 8; i++) { ts += sh[i]; ts2 += sh[i + 32]; }
        float mu = ts / D_DIM;
        sh[0] = mu;
        sh[1] = rsqrtf(ts2 / D_DIM - mu * mu + 1e-5f);
    }
    __syncthreads();
    float mu = sh[0], rstd = sh[1];
    for (int i = threadIdx.x; i < D_DIM; i += 256)
        out[(size_t)row * D_DIM + i] = (xr[i] - mu) * rstd * g[i] + b[i];
}

// ---------------- bf16-split tensor-core GEMM (NT), double-buffered --------
// C[M,N] = A[M,K] @ B[N,K]^T + epilogue, fp32 in/out.
// Each fp32 = hi_bf16 + lo_bf16; per k16: mma(hi,hi)+mma(hi,lo)+mma(lo,hi).
enum { EPI_BIAS = 0, EPI_PHI = 1, EPI_GELU = 2, EPI_RES = 3 };

struct GemmBatch {
    const float* W[3];
    const float* bias[3];
    float*       out[3];
    int          epi[3];
};

__device__ __forceinline__ void mma_bf16(float* c, const unsigned* a, const unsigned* b) {
    asm volatile(
        "mma.sync.aligned.m16n8k16.row.col.f32.bf16.bf16.f32 "
        "{%0,%1,%2,%3}, {%4,%5,%6,%7}, {%8,%9}, {%0,%1,%2,%3};\n"
        : "+f"(c[0]), "+f"(c[1]), "+f"(c[2]), "+f"(c[3])
        : "r"(a[0]), "r"(a[1]), "r"(a[2]), "r"(a[3]), "r"(b[0]), "r"(b[1]));
}

__device__ __forceinline__ uint2 cvt_hi_lo(float4 v, uint2& lo) {
    __nv_bfloat16 hx = __float2bfloat16(v.x);
    __nv_bfloat16 hy = __float2bfloat16(v.y);
    __nv_bfloat16 hz = __float2bfloat16(v.z);
    __nv_bfloat16 hw = __float2bfloat16(v.w);
    __nv_bfloat16 lx = __float2bfloat16(v.x - __bfloat162float(hx));
    __nv_bfloat16 ly = __float2bfloat16(v.y - __bfloat162float(hy));
    __nv_bfloat16 lz = __float2bfloat16(v.z - __bfloat162float(hz));
    __nv_bfloat16 lw = __float2bfloat16(v.w - __bfloat162float(hw));
    lo.x = (uint32_t)__bfloat16_as_ushort(lx) | ((uint32_t)__bfloat16_as_ushort(ly) << 16);
    lo.y = (uint32_t)__bfloat16_as_ushort(lz) | ((uint32_t)__bfloat16_as_ushort(lw) << 16);
    uint2 hi;
    hi.x = (uint32_t)__bfloat16_as_ushort(hx) | ((uint32_t)__bfloat16_as_ushort(hy) << 16);
    hi.y = (uint32_t)__bfloat16_as_ushort(hz) | ((uint32_t)__bfloat16_as_ushort(hw) << 16);
    return hi;
}

#define LDSW 40
#define TSZ  (128 * LDSW)            // bf16 elems per tile
#define STG  (4 * TSZ)               // bf16 elems per stage
#define SMEM_GEMM (2 * STG * 2)      // bytes (81920)

__global__ __launch_bounds__(256, 1)
void gemm_mma(const float* __restrict__ A, GemmBatch bt,
              const float* __restrict__ res, int M, int N, int K) {
    extern __shared__ __align__(16) __nv_bfloat16 SM[];
    const int z = blockIdx.z;
    const float* B    = bt.W[z];
    const float* bias = bt.bias[z];
    float*       Cmat = bt.out[z];
    const int    epi  = bt.epi[z];

    const int tid  = threadIdx.x;
    const int bm   = blockIdx.y * 128, bn = blockIdx.x * 128;
    const int lane = tid & 31, warp = tid >> 5;
    const int wm   = (warp & 3) * 32;
    const int wn   = (warp >> 2) * 64;
    const int g    = lane >> 2;
    const int tg   = (lane & 3) * 2;

    const int lrow = tid >> 3;            // 0..31
    const int lcol = (tid & 7) * 4;       // 0,4,...,28

    float acc[2][8][4];
#pragma unroll
    for (int i = 0; i < 2; i++)
#pragma unroll
        for (int j = 0; j < 8; j++)
#pragma unroll
            for (int e = 0; e < 4; e++) acc[i][j][e] = 0.f;

    const float* Ap = A + (size_t)(bm + lrow) * K + lcol;
    const float* Bp = B + (size_t)(bn + lrow) * K + lcol;

    float4 ar[4], br[4];
#pragma unroll
    for (int i = 0; i < 4; i++) {
        ar[i] = *(const float4*)(Ap + (size_t)(32 * i) * K);
        br[i] = *(const float4*)(Bp + (size_t)(32 * i) * K);
    }

    // store regs -> stage s
    auto sts_stage = [&](int s) {
        __nv_bfloat16* Ah = SM + s * STG;
        __nv_bfloat16* Al = Ah + TSZ;
        __nv_bfloat16* Bh = Ah + 2 * TSZ;
        __nv_bfloat16* Bl = Ah + 3 * TSZ;
#pragma unroll
        for (int i = 0; i < 4; i++) {
            int r = lrow + 32 * i;
            uint2 lo, hi;
            hi = cvt_hi_lo(ar[i], lo);
            *(uint2*)&Ah[r * LDSW + lcol] = hi;
            *(uint2*)&Al[r * LDSW + lcol] = lo;
            hi = cvt_hi_lo(br[i], lo);
            *(uint2*)&Bh[r * LDSW + lcol] = hi;
            *(uint2*)&Bl[r * LDSW + lcol] = lo;
        }
    };

    sts_stage(0);
    __syncthreads();

    const int nb = K / 32;
    for (int t = 0; t < nb; t++) {
        const int s = t & 1;
        if (t + 1 < nb) {
            int kt = (t + 1) * 32;
#pragma unroll
            for (int i = 0; i < 4; i++) {
                ar[i] = *(const float4*)(Ap + kt + (size_t)(32 * i) * K);
                br[i] = *(const float4*)(Bp + kt + (size_t)(32 * i) * K);
            }
        }
        const __nv_bfloat16* Ah = SM + s * STG;
        const __nv_bfloat16* Al = Ah + TSZ;
        const __nv_bfloat16* Bh = Ah + 2 * TSZ;
        const __nv_bfloat16* Bl = Ah + 3 * TSZ;
#pragma unroll
        for (int kk = 0; kk < 32; kk += 16) {
            unsigned ah[2][4], al[2][4], bh[8][2], bl[8][2];
#pragma unroll
            for (int mi = 0; mi < 2; mi++) {
                int r0 = wm + mi * 16 + g;
                ah[mi][0] = *(const unsigned*)&Ah[(r0    ) * LDSW + kk + tg    ];
                ah[mi][1] = *(const unsigned*)&Ah[(r0 + 8) * LDSW + kk + tg    ];
                ah[mi][2] = *(const unsigned*)&Ah[(r0    ) * LDSW + kk + tg + 8];
                ah[mi][3] = *(const unsigned*)&Ah[(r0 + 8) * LDSW + kk + tg + 8];
                al[mi][0] = *(const unsigned*)&Al[(r0    ) * LDSW + kk + tg    ];
                al[mi][1] = *(const unsigned*)&Al[(r0 + 8) * LDSW + kk + tg    ];
                al[mi][2] = *(const unsigned*)&Al[(r0    ) * LDSW + kk + tg + 8];
                al[mi][3] = *(const unsigned*)&Al[(r0 + 8) * LDSW + kk + tg + 8];
            }
#pragma unroll
            for (int ni = 0; ni < 8; ni++) {
                int c0 = wn + ni * 8 + g;
                bh[ni][0] = *(const unsigned*)&Bh[c0 * LDSW + kk + tg    ];
                bh[ni][1] = *(const unsigned*)&Bh[c0 * LDSW + kk + tg + 8];
                bl[ni][0] = *(const unsigned*)&Bl[c0 * LDSW + kk + tg    ];
                bl[ni][1] = *(const unsigned*)&Bl[c0 * LDSW + kk + tg + 8];
            }
#pragma unroll
            for (int mi = 0; mi < 2; mi++)
#pragma unroll
                for (int ni = 0; ni < 8; ni++) {
                    mma_bf16(acc[mi][ni], ah[mi], bh[ni]);
                    mma_bf16(acc[mi][ni], ah[mi], bl[ni]);
                    mma_bf16(acc[mi][ni], al[mi], bh[ni]);
                }
        }
        if (t + 1 < nb) {
            sts_stage((t + 1) & 1);
            __syncthreads();
        }
    }

    // epilogue
#pragma unroll
    for (int mi = 0; mi < 2; mi++)
#pragma unroll
        for (int ni = 0; ni < 8; ni++) {
            int r0 = bm + wm + mi * 16 + g;
            int c0 = bn + wn + ni * 8 + tg;
#pragma unroll
            for (int half = 0; half < 2; half++) {
                int r = r0 + half * 8;
                float v0 = acc[mi][ni][half * 2 + 0] + bias[c0];
                float v1 = acc[mi][ni][half * 2 + 1] + bias[c0 + 1];
                if (epi == EPI_PHI) {
                    v0 = (v0 > 0.f) ? (v0 + 1.f) : expf(v0);
                    v1 = (v1 > 0.f) ? (v1 + 1.f) : expf(v1);
                } else if (epi == EPI_GELU) {
                    v0 = 0.5f * v0 * (1.f + erff(v0 * 0.70710678118654752f));
                    v1 = 0.5f * v1 * (1.f + erff(v1 * 0.70710678118654752f));
                } else if (epi == EPI_RES) {
                    float2 rv = *(const float2*)(res + (size_t)r * N + c0);
                    v0 += rv.x; v1 += rv.y;
                }
                float2 o = make_float2(v0, v1);
                *(float2*)(Cmat + (size_t)r * N + c0) = o;
            }
        }
}

// ---------------- Pass A: per-chunk KV sums -------------------------------
__global__ void chunk_kv_kernel() {
    __shared__ float ks[CCH * (HDIM + 1)];
    __shared__ float vs[CCH * (HDIM + 1)];
    int blk = blockIdx.x, h = blk / NCH, c = blk % NCH, tid = threadIdx.x;
    int s0 = c * CCH;
    for (int i = tid; i < CCH * HDIM; i += 256) {
        int r = i >> 6, d = i & 63;
        ks[r * (HDIM + 1) + d] = g_k[(size_t)(s0 + r) * D_DIM + h * HDIM + d];
        vs[r * (HDIM + 1) + d] = g_v[(size_t)(s0 + r) * D_DIM + h * HDIM + d];
    }
    __syncthreads();
    int d = tid >> 2, e0 = (tid & 3) * 16;
    float acc[16] = {};
    for (int s = 0; s < CCH; s++) {
        float kd = ks[s * (HDIM + 1) + d];
#pragma unroll
        for (int j = 0; j < 16; j++)
            acc[j] += kd * vs[s * (HDIM + 1) + e0 + j];
    }
    float* outp = g_kv + ((size_t)(h * NCH + c) * HDIM + d) * HDIM + e0;
#pragma unroll
    for (int j = 0; j < 16; j++) outp[j] = acc[j];
    if (tid < HDIM) {
        float z = 0.f;
        for (int s = 0; s < CCH; s++) z += ks[s * (HDIM + 1) + tid];
        g_zc[(h * NCH + c) * HDIM + tid] = z;
    }
}

// ---------------- Pass B: exclusive prefix over chunks --------------------
__global__ void prefix_kernel() {
    int idx = blockIdx.x * 256 + threadIdx.x;
    int h = idx / (HDIM * HDIM), de = idx % (HDIM * HDIM);
    float run = 0.f;
    for (int c = 0; c < NCH; c++) {
        size_t off = ((size_t)(h * NCH + c) * HDIM * HDIM) + de;
        float v = g_kv[off];
        g_kvp[off] = run;
        run += v;
    }
    if (idx < H_NUM * HDIM) {
        int ho = idx / HDIM, dd = idx % HDIM;
        float rz = 0.f;
        for (int c = 0; c < NCH; c++) {
            int off = (ho * NCH + c) * HDIM + dd;
            float v = g_zc[off];
            g_zp[off] = rz;
            rz += v;
        }
    }
}

// ---------------- Pass C: per-chunk attention output ----------------------
__global__ void chunk_attn_kernel() {
    extern __shared__ float sm[];
    float* qs = sm;
    float* kv = qs + CCH * (HDIM + 1);
    float* Ss = kv + CCH * (HDIM + 1);
    float* kp = Ss + CCH * (CCH + 1);
    float* zp = kp + HDIM * (HDIM + 1);
    float* dn = zp + HDIM;

    int blk = blockIdx.x, h = blk / NCH, c = blk % NCH, tid = threadIdx.x;
    int s0 = c * CCH;

    for (int i = tid; i < CCH * HDIM; i += 256) {
        int r = i >> 6, d = i & 63;
        qs[r * (HDIM + 1) + d] = g_q[(size_t)(s0 + r) * D_DIM + h * HDIM + d];
        kv[r * (HDIM + 1) + d] = g_k[(size_t)(s0 + r) * D_DIM + h * HDIM + d];
        kp[r * (HDIM + 1) + d] = g_kvp[((size_t)(h * NCH + c) * HDIM + r) * HDIM + d];
    }
    if (tid < HDIM) zp[tid] = g_zp[(h * NCH + c) * HDIM + tid];
    __syncthreads();

    {
        int t = tid >> 2, i0 = (tid & 3) * 16;
        for (int j = 0; j < 16; j++) {
            int i = i0 + j;
            float sc = 0.f;
            if (i <= t) {
#pragma unroll
                for (int d = 0; d < HDIM; d++)
                    sc += qs[t * (HDIM + 1) + d] * kv[i * (HDIM + 1) + d];
            }
            Ss[t * (CCH + 1) + i] = sc;
        }
    }
    __syncthreads();

    if (tid < CCH) {
        float dd = 1e-6f;
        for (int d = 0; d < HDIM; d++)
            dd += qs[tid * (HDIM + 1) + d] * zp[d];
        for (int i = 0; i < CCH; i++)
            dd += Ss[tid * (CCH + 1) + i];
        dn[tid] = dd;
    }
    for (int i = tid; i < CCH * HDIM; i += 256) {
        int r = i >> 6, d = i & 63;
        kv[r * (HDIM + 1) + d] = g_v[(size_t)(s0 + r) * D_DIM + h * HDIM + d];
    }
    __syncthreads();

    int t = tid >> 2, e0 = (tid & 3) * 16;
    float o[16] = {};
    for (int d = 0; d < HDIM; d++) {
        float qd = qs[t * (HDIM + 1) + d];
#pragma unroll
        for (int j = 0; j < 16; j++)
            o[j] += qd * kp[d * (HDIM + 1) + e0 + j];
    }
    for (int i = 0; i < CCH; i++) {
        float sv = Ss[t * (CCH + 1) + i];
#pragma unroll
        for (int j = 0; j < 16; j++)
            o[j] += sv * kv[i * (HDIM + 1) + e0 + j];
    }
    float inv = 1.f / dn[t];
    float* op = g_attn + (size_t)(s0 + t) * D_DIM + h * HDIM + e0;
#pragma unroll
    for (int j = 0; j < 16; j++) op[j] = o[j] * inv;
}

// ---------------- launch ---------------------------------------------------
extern "C" void kernel_launch(void* const* d_in, const int* in_sizes, int n_in,
                              void* d_out, int out_size) {
    const float* x   = (const float*)d_in[0];
    const float* Wq  = (const float*)d_in[1];  const float* bq  = (const float*)d_in[2];
    const float* Wk  = (const float*)d_in[3];  const float* bk  = (const float*)d_in[4];
    const float* Wv  = (const float*)d_in[5];  const float* bv  = (const float*)d_in[6];
    const float* Wo  = (const float*)d_in[7];  const float* bo  = (const float*)d_in[8];
    const float* W1  = (const float*)d_in[9];  const float* b1  = (const float*)d_in[10];
    const float* W2  = (const float*)d_in[11]; const float* b2  = (const float*)d_in[12];
    const float* g1  = (const float*)d_in[13]; const float* be1 = (const float*)d_in[14];
    const float* g2  = (const float*)d_in[15]; const float* be2 = (const float*)d_in[16];
    float* out = (float*)d_out;

    float *h, *q, *k, *v, *attn, *x2, *h2, *ff;
    cudaGetSymbolAddress((void**)&h,    g_h);
    cudaGetSymbolAddress((void**)&q,    g_q);
    cudaGetSymbolAddress((void**)&k,    g_k);
    cudaGetSymbolAddress((void**)&v,    g_v);
    cudaGetSymbolAddress((void**)&attn, g_attn);
    cudaGetSymbolAddress((void**)&x2,   g_x2);
    cudaGetSymbolAddress((void**)&h2,   g_h2);
    cudaGetSymbolAddress((void**)&ff,   g_ff);

    cudaFuncSetAttribute(gemm_mma, cudaFuncAttributeMaxDynamicSharedMemorySize, SMEM_GEMM);

    const int smem_attn = (2 * CCH * (HDIM + 1) + CCH * (CCH + 1) +
                           HDIM * (HDIM + 1) + HDIM + CCH) * (int)sizeof(float);
    cudaFuncSetAttribute(chunk_attn_kernel,
                         cudaFuncAttributeMaxDynamicSharedMemorySize, smem_attn);

    dim3 gQKV(D_DIM / 128, S_LEN / 128, 3);
    dim3 gD(D_DIM / 128, S_LEN / 128, 1);
    dim3 gF(FF_DIM / 128, S_LEN / 128, 1);

    ln_kernel<<<S_LEN, 256>>>(x, g1, be1, h);

    GemmBatch bqkv;
    bqkv.W[0] = Wq; bqkv.bias[0] = bq; bqkv.out[0] = q; bqkv.epi[0] = EPI_PHI;
    bqkv.W[1] = Wk; bqkv.bias[1] = bk; bqkv.out[1] = k; bqkv.epi[1] = EPI_PHI;
    bqkv.W[2] = Wv; bqkv.bias[2] = bv; bqkv.out[2] = v; bqkv.epi[2] = EPI_BIAS;
    gemm_mma<<<gQKV, 256, SMEM_GEMM>>>(h, bqkv, nullptr, S_LEN, D_DIM, D_DIM);

    chunk_kv_kernel  <<<H_NUM * NCH, 256>>>();
    prefix_kernel    <<<H_NUM * HDIM * HDIM / 256, 256>>>();
    chunk_attn_kernel<<<H_NUM * NCH, 256, smem_attn>>>();

    GemmBatch bo_b;
    bo_b.W[0] = Wo; bo_b.bias[0] = bo; bo_b.out[0] = x2; bo_b.epi[0] = EPI_RES;
    gemm_mma<<<gD, 256, SMEM_GEMM>>>(attn, bo_b, x, S_LEN, D_DIM, D_DIM);

    ln_kernel<<<S_LEN, 256>>>(x2, g2, be2, h2);

    GemmBatch bf1;
    bf1.W[0] = W1; bf1.bias[0] = b1; bf1.out[0] = ff; bf1.epi[0] = EPI_GELU;
    gemm_mma<<<gF, 256, SMEM_GEMM>>>(h2, bf1, nullptr, S_LEN, FF_DIM, D_DIM);

    GemmBatch bf2;
    bf2.W[0] = W2; bf2.bias[0] = b2; bf2.out[0] = out; bf2.epi[0] = EPI_RES;
    gemm_mma<<<gD, 256, SMEM_GEMM>>>(ff, bf2, x2, S_LEN, D_DIM, FF_DIM);
}